// round 2
// baseline (speedup 1.0000x reference)
#include <cuda_runtime.h>
#include <math.h>

// ---------------------------------------------------------------------------
// Fused IFS generator chain, fp32 SIMT baseline.
//   h  = relu(LN(z @ W1 + b1))
//   ya = silu(LN(h @ Wa + ba))
//   yb = LN(ya @ Wb + bb)
//   h2 = h + yb
//   x  = h2 @ Wout + bout
//   affines = clamp-SVD(x[:,:30]) ; probs = softmax(x[:,30:35])
// One CTA = 32 rows, all intermediates in smem (k-major, stride 33).
// ---------------------------------------------------------------------------

#define TB      32          // rows per CTA
#define THREADS 256
#define ST      33          // padded row stride in smem (k-major [col][row])

#define LATENT  256
#define MID     512
#define OUTW    35
#define NT      5
#define EPSV    1e-5f
#define THRESH  0.9f

// smem float layout
#define BUFF      (MID * ST)          // 16896 floats per activation buffer
#define SW_OFF    (3 * BUFF)          // weight staging: 8 x 512 = 4096 floats
#define SX_OFF    (SW_OFF + 4096)     // final x tile: 32 x 36
#define SMEM_F    (SX_OFF + TB * 36)  // 55936 floats = 223744 bytes

// ---------------------------------------------------------------------------
// GEMM: sOut[n][r] = sum_k sA[k][r] * W[k][n] + bias[n]   (N = 512 fixed)
// sA, sOut are k-major with stride ST. Weights staged 8 k-rows at a time.
// Thread tile: 8 rows x 8 cols (rows broadcast within warp -> free LDS).
// ---------------------------------------------------------------------------
__device__ __forceinline__ void gemm512(const float* __restrict__ sA, int K,
                                        const float* __restrict__ W,
                                        const float* __restrict__ bias,
                                        float* __restrict__ sOut,
                                        float* __restrict__ sW, int tid)
{
    const int r0 = (tid >> 6) * 8;        // row group (4 groups of 8)
    const int c0 = (tid & 63) * 8;        // col group (64 groups of 8)

    float acc[8][8];
#pragma unroll
    for (int i = 0; i < 8; i++)
#pragma unroll
        for (int j = 0; j < 8; j++) acc[i][j] = 0.f;

    for (int k0 = 0; k0 < K; k0 += 8) {
        __syncthreads();                  // previous sW fully consumed
        // stage W[k0:k0+8][0:512] -> sW (4096 floats, 4 float4 per thread)
#pragma unroll
        for (int it = 0; it < 4; it++) {
            int idx = tid + it * THREADS;         // 0..1023 (float4 index)
            int k  = idx >> 7;
            int f4 = idx & 127;
            *(float4*)&sW[k * 512 + f4 * 4] =
                *(const float4*)&W[(size_t)(k0 + k) * 512 + f4 * 4];
        }
        __syncthreads();

#pragma unroll
        for (int k = 0; k < 8; k++) {
            const float* ap = sA + (k0 + k) * ST + r0;
            float a[8];
#pragma unroll
            for (int i = 0; i < 8; i++) a[i] = ap[i];   // warp-broadcast LDS

            const float* wp = sW + k * 512 + c0;
            float4 w0 = *(const float4*)wp;
            float4 w1 = *(const float4*)(wp + 4);
            float w[8] = {w0.x, w0.y, w0.z, w0.w, w1.x, w1.y, w1.z, w1.w};

#pragma unroll
            for (int i = 0; i < 8; i++)
#pragma unroll
                for (int j = 0; j < 8; j++)
                    acc[i][j] = fmaf(a[i], w[j], acc[i][j]);
        }
    }
    __syncthreads();

#pragma unroll
    for (int j = 0; j < 8; j++) {
        float bj = bias[c0 + j];
#pragma unroll
        for (int i = 0; i < 8; i++)
            sOut[(c0 + j) * ST + r0 + i] = acc[i][j] + bj;
    }
}

// ---------------------------------------------------------------------------
// In-place layernorm over 512 cols of each row, then activation.
// act: 0 = none, 1 = relu, 2 = silu.  One warp handles 4 rows.
// ---------------------------------------------------------------------------
__device__ __forceinline__ void ln_act(float* __restrict__ sBuf,
                                       const float* __restrict__ g,
                                       const float* __restrict__ be,
                                       int act, int tid)
{
    __syncthreads();
    const int warp = tid >> 5, lane = tid & 31;
#pragma unroll
    for (int rr = 0; rr < 4; rr++) {
        const int r = warp * 4 + rr;
        float s = 0.f, s2 = 0.f;
        for (int c = lane; c < MID; c += 32) {
            float v = sBuf[c * ST + r];
            s += v; s2 += v * v;
        }
#pragma unroll
        for (int o = 16; o; o >>= 1) {
            s  += __shfl_xor_sync(0xffffffffu, s,  o);
            s2 += __shfl_xor_sync(0xffffffffu, s2, o);
        }
        const float mu   = s * (1.f / MID);
        const float var  = fmaxf(s2 * (1.f / MID) - mu * mu, 0.f);
        const float rstd = 1.f / sqrtf(var + EPSV);
        for (int c = lane; c < MID; c += 32) {
            float v = (sBuf[c * ST + r] - mu) * rstd * g[c] + be[c];
            if (act == 1)      v = fmaxf(v, 0.f);
            else if (act == 2) v = v * (1.f / (1.f + expf(-v)));
            sBuf[c * ST + r] = v;
        }
    }
    __syncthreads();
}

// ---------------------------------------------------------------------------
__global__ void __launch_bounds__(THREADS, 1)
ifs_kernel(const float* __restrict__ z,
           const float* __restrict__ W1, const float* __restrict__ b1,
           const float* __restrict__ g1, const float* __restrict__ be1,
           const float* __restrict__ Wa, const float* __restrict__ ba,
           const float* __restrict__ ga, const float* __restrict__ bea,
           const float* __restrict__ Wb, const float* __restrict__ bb,
           const float* __restrict__ gb, const float* __restrict__ beb,
           const float* __restrict__ Wout, const float* __restrict__ bout,
           float* __restrict__ out, int Btot)
{
    extern __shared__ float sm[];
    float* buf0 = sm;                 // z -> u -> yb -> h2
    float* buf1 = sm + BUFF;          // h
    float* buf2 = sm + 2 * BUFF;      // ya
    float* sW   = sm + SW_OFF;
    float* sX   = sm + SX_OFF;

    const int tid  = threadIdx.x;
    const int row0 = blockIdx.x * TB;

    // load z tile k-major into buf0
    for (int i = tid; i < TB * (LATENT / 4); i += THREADS) {
        int r  = i >> 6;              // 0..31
        int c4 = i & 63;              // 0..63 float4 within row
        float4 v = *(const float4*)&z[(size_t)(row0 + r) * LATENT + c4 * 4];
        buf0[(c4 * 4 + 0) * ST + r] = v.x;
        buf0[(c4 * 4 + 1) * ST + r] = v.y;
        buf0[(c4 * 4 + 2) * ST + r] = v.z;
        buf0[(c4 * 4 + 3) * ST + r] = v.w;
    }
    __syncthreads();

    gemm512(buf0, LATENT, W1, b1, buf1, sW, tid);   // h_pre
    ln_act(buf1, g1, be1, /*relu*/1, tid);          // h
    gemm512(buf1, MID, Wa, ba, buf2, sW, tid);      // ya_pre
    ln_act(buf2, ga, bea, /*silu*/2, tid);          // ya
    gemm512(buf2, MID, Wb, bb, buf0, sW, tid);      // u
    ln_act(buf0, gb, beb, /*none*/0, tid);          // yb

    // h2 = h + yb  (into buf0)
    for (int i = tid; i < MID * TB; i += THREADS) {
        int c = i >> 5, r = i & 31;
        buf0[c * ST + r] += buf1[c * ST + r];
    }
    __syncthreads();

    // x = h2 @ Wout + bout -> sX[r][j]  (35 cols, stride 36)
    {
        const int r = tid >> 3, jt = tid & 7;
        float acc[5] = {0.f, 0.f, 0.f, 0.f, 0.f};
        for (int k0 = 0; k0 < MID; k0 += 8) {
            __syncthreads();
            for (int i = tid; i < 8 * OUTW; i += THREADS) {
                int k = i / OUTW, n = i % OUTW;
                sW[k * 36 + n] = Wout[(size_t)(k0 + k) * OUTW + n];
            }
            __syncthreads();
#pragma unroll
            for (int k = 0; k < 8; k++) {
                float a = buf0[(k0 + k) * ST + r];
#pragma unroll
                for (int m = 0; m < 5; m++) {
                    int j = jt + 8 * m;
                    if (j < OUTW) acc[m] = fmaf(a, sW[k * 36 + j], acc[m]);
                }
            }
        }
        __syncthreads();
#pragma unroll
        for (int m = 0; m < 5; m++) {
            int j = jt + 8 * m;
            if (j < OUTW) sX[r * 36 + j] = acc[m] + bout[j];
        }
    }
    __syncthreads();

    // --- postprocess: per (row, transform) closed-form 2x2 SVD clamp ---
    // M = Q*Rot(a2) + R*Ref(a1); s1 = Q+R, s2 = Q-R. Clamping singular values
    // (s1 -> min(s1,t), s2 -> clamp(s2,-t,t)) == rescaling Q,R with fixed
    // rotation/reflection parts: M2 = rQ*[[E,-H],[H,E]] + rR*[[F,G],[G,-F]].
    if (tid < TB * NT) {
        const int r = tid / NT, t = tid % NT;
        const size_t gr = (size_t)(row0 + r);
        const float* xp = &sX[r * 36 + t * 6];
        float a = xp[0], b = xp[1], tx = xp[2];
        float c = xp[3], d = xp[4], ty = xp[5];

        float E = 0.5f * (a + d), F = 0.5f * (a - d);
        float G = 0.5f * (c + b), H = 0.5f * (c - b);
        float Q = sqrtf(E * E + H * H);
        float R = sqrtf(F * F + G * G);
        float s1 = Q + R, s2 = Q - R;
        float s1c = fminf(s1, THRESH);
        float s2c = fminf(fmaxf(s2, -THRESH), THRESH);
        float Qc = 0.5f * (s1c + s2c), Rc = 0.5f * (s1c - s2c);
        float rQ = Qc / fmaxf(Q, 1e-30f);
        float rR = Rc / fmaxf(R, 1e-30f);

        float na =  rQ * E + rR * F;
        float nb = -rQ * H + rR * G;
        float nc =  rQ * H + rR * G;
        float nd =  rQ * E - rR * F;

        float* op = out + (gr * NT + t) * 6;
        op[0] = na; op[1] = nb; op[2] = tx;
        op[3] = nc; op[4] = nd; op[5] = ty;
    }

    // --- softmax over 5 logits per row ---
    if (tid < TB) {
        const int r = tid;
        const size_t gr = (size_t)(row0 + r);
        float l[5], mx = -1e30f;
#pragma unroll
        for (int k = 0; k < 5; k++) { l[k] = sX[r * 36 + 30 + k]; mx = fmaxf(mx, l[k]); }
        float ssum = 0.f;
#pragma unroll
        for (int k = 0; k < 5; k++) { l[k] = expf(l[k] - mx); ssum += l[k]; }
        float inv = 1.f / ssum;
        float* op = out + (size_t)Btot * (NT * 6) + gr * NT;
#pragma unroll
        for (int k = 0; k < 5; k++) op[k] = l[k] * inv;
    }
}

// ---------------------------------------------------------------------------
extern "C" void kernel_launch(void* const* d_in, const int* in_sizes, int n_in,
                              void* d_out, int out_size)
{
    const float* z    = (const float*)d_in[0];
    const float* W1   = (const float*)d_in[1];
    const float* b1   = (const float*)d_in[2];
    const float* g1   = (const float*)d_in[3];
    const float* be1  = (const float*)d_in[4];
    const float* Wa   = (const float*)d_in[5];
    const float* ba   = (const float*)d_in[6];
    const float* ga   = (const float*)d_in[7];
    const float* bea  = (const float*)d_in[8];
    const float* Wb   = (const float*)d_in[9];
    const float* bb   = (const float*)d_in[10];
    const float* gb   = (const float*)d_in[11];
    const float* gbeb = (const float*)d_in[12];
    const float* Wout = (const float*)d_in[13];
    const float* bout = (const float*)d_in[14];
    float* out = (float*)d_out;

    const int Btot = in_sizes[0] / LATENT;
    const int smem_bytes = SMEM_F * sizeof(float);

    cudaFuncSetAttribute(ifs_kernel,
                         cudaFuncAttributeMaxDynamicSharedMemorySize, smem_bytes);

    ifs_kernel<<<Btot / TB, THREADS, smem_bytes>>>(
        z, W1, b1, g1, be1, Wa, ba, ga, bea, Wb, bb, gb, gbeb,
        Wout, bout, out, Btot);
}

// round 6
// speedup vs baseline: 6.6842x; 6.6842x over previous
#include <cuda_runtime.h>
#include <cuda_fp16.h>
#include <math.h>

// ===========================================================================
// Fused IFS generator on mma.sync (HMMA) — family-target safe (no tcgen05).
//   h  = relu(LN(z @ W1 + b1));  ya = silu(LN(h @ Wa + ba));
//   yb = LN(ya @ Wb + bb);  h2 = h + yb;  x = h2 @ Wout + bout
//   out = [clamp-SVD(x[:,:30]) , softmax(x[:,30:35])]
// 1 CTA = 128 rows, 256 threads (8 warps, 4Mx2N warp grid, tile 32x64).
// A: fp16 smem [128][520], in-place per layer. W: pre-transposed fp16 in
// global (prep kernels), streamed via double-buffered cp.async.
// Pre-LN x stashed fp16 in registers; LN stats via shfl + shared atomics.
// ===========================================================================

#define THREADS 256
#define EPSV    1e-5f
#define THRESH  0.9f

#define A_STRIDE_B  1040          // 520 halves per A row (conflict-free ldmatrix)
#define WS_STRIDE_B 144           // 72 halves per staged WT row
#define WS_OFF      133120        // A = 128*1040
#define WS_BUF      18432         // 128 rows * 144 B
#define P_OFF       (WS_OFF + 2*WS_BUF)    // 169984
#define RED_OFF     (P_OFF + 18688)        // 188672
#define SMEM_BYTES  (RED_OFF + 1024)       // 189696

// pre-transposed fp16 weights WT[n][k] = W[k][n]
__device__ __align__(16) __half g_Wt1[512 * 256];
__device__ __align__(16) __half g_Wta[512 * 512];
__device__ __align__(16) __half g_Wtb[512 * 512];
__device__ __align__(16) __half g_Wto[64 * 512];        // rows 35..63 zero
// residual h scratch (fp16)
__device__ __align__(16) __half g_h[(size_t)131072 * 512];

// ---------------- asm helpers (all sm_80-baseline legal) ----------------
__device__ __forceinline__ unsigned smem_u32(const void* p) {
    unsigned a;
    asm("{ .reg .u64 t; cvta.to.shared.u64 t, %1; cvt.u32.u64 %0, t; }"
        : "=r"(a) : "l"(p));
    return a;
}

#define LDMX4(r0, r1, r2, r3, addr) \
    asm volatile("ldmatrix.sync.aligned.m8n8.x4.shared.b16 {%0,%1,%2,%3}, [%4];" \
                 : "=r"(r0), "=r"(r1), "=r"(r2), "=r"(r3) : "r"(addr))

#define MMA16816(c, a, b) \
    asm volatile("mma.sync.aligned.m16n8k16.row.col.f32.f16.f16.f32 " \
                 "{%0,%1,%2,%3},{%4,%5,%6,%7},{%8,%9},{%0,%1,%2,%3};" \
                 : "+f"((c)[0]), "+f"((c)[1]), "+f"((c)[2]), "+f"((c)[3]) \
                 : "r"((a)[0]), "r"((a)[1]), "r"((a)[2]), "r"((a)[3]), \
                   "r"((b)[0]), "r"((b)[1]))

#define CP_ASYNC16(dst, src) \
    asm volatile("cp.async.ca.shared.global [%0], [%1], 16;" \
                 :: "r"(dst), "l"(src))
#define CP_COMMIT() asm volatile("cp.async.commit_group;")
#define CP_WAIT1()  asm volatile("cp.async.wait_group 1;")
#define CP_WAIT0()  asm volatile("cp.async.wait_group 0;")

#define STS32(addr, v) \
    asm volatile("st.shared.b32 [%0], %1;" :: "r"(addr), "r"(v))
#define STS64(addr, v0, v1) \
    asm volatile("st.shared.v2.b32 [%0], {%1,%2};" :: "r"(addr), "r"(v0), "r"(v1))
#define LDS128(v0, v1, v2, v3, addr) \
    asm volatile("ld.shared.v4.b32 {%0,%1,%2,%3}, [%4];" \
                 : "=r"(v0), "=r"(v1), "=r"(v2), "=r"(v3) : "r"(addr))
#define STS128(addr, v0, v1, v2, v3) \
    asm volatile("st.shared.v4.b32 [%0], {%1,%2,%3,%4};" \
                 :: "r"(addr), "r"(v0), "r"(v1), "r"(v2), "r"(v3))

// ---------------------------------------------------------------------------
// stage a [nrows][64 k] fp16 tile of WT (row stride Kdim halves) into smem
__device__ __forceinline__ void stage(const __half* __restrict__ WTg, int Kdim,
                                      int nrows, int n0, int ks,
                                      unsigned dstBase, int tid)
{
    for (int c = tid; c < nrows * 8; c += THREADS) {
        int row = c >> 3, seg = c & 7;
        const char* src = (const char*)(WTg + (size_t)(n0 + row) * Kdim + ks * 64)
                          + seg * 16;
        CP_ASYNC16(dstBase + (unsigned)(row * WS_STRIDE_B + seg * 16), src);
    }
    CP_COMMIT();
}

// ---------------------------------------------------------------------------
// one N-chunk GEMM: acc[2][NT][4] += A[128][Kdim] @ WT[n0..][Kdim]^T slice
template <int NT>
__device__ __forceinline__ void gemm_chunk(const __half* __restrict__ WTg,
                                           int Kdim, int nrows, int n0,
                                           unsigned sbA, unsigned sbW,
                                           float (&acc)[2][NT][4],
                                           int tid, int lane, int mi, int ni)
{
#pragma unroll
    for (int mt = 0; mt < 2; mt++)
#pragma unroll
        for (int nt = 0; nt < NT; nt++)
#pragma unroll
            for (int q = 0; q < 4; q++) acc[mt][nt][q] = 0.f;

    const unsigned aRS = (((unsigned)lane >> 3) & 1u) * 8u + ((unsigned)lane & 7u);
    const unsigned aCS = ((unsigned)lane >> 4) << 4;
    const unsigned bRS = (((unsigned)lane >> 4) << 3) + ((unsigned)lane & 7u);
    const unsigned bCS = (((unsigned)lane >> 3) & 1u) << 4;
    const unsigned aBase = sbA + (unsigned)(mi * 32 + aRS) * A_STRIDE_B + aCS;
    const unsigned bOff  = (unsigned)(ni * NT * 8 + bRS) * WS_STRIDE_B + bCS;

    const int S = Kdim >> 6;
    stage(WTg, Kdim, nrows, n0, 0, sbW, tid);
    for (int ks = 0; ks < S; ks++) {
        const unsigned cur = sbW + (unsigned)(ks & 1) * WS_BUF;
        if (ks + 1 < S) {
            stage(WTg, Kdim, nrows, n0, ks + 1, sbW + (unsigned)((ks + 1) & 1) * WS_BUF, tid);
            CP_WAIT1();
        } else {
            CP_WAIT0();
        }
        __syncthreads();
#pragma unroll
        for (int ki = 0; ki < 4; ki++) {
            const unsigned kb = (unsigned)(ks * 64 + ki * 16) * 2u;
            unsigned a[2][4];
#pragma unroll
            for (int mt = 0; mt < 2; mt++)
                LDMX4(a[mt][0], a[mt][1], a[mt][2], a[mt][3],
                      aBase + (unsigned)(mt * 16) * A_STRIDE_B + kb);
            unsigned b[NT][2];
#pragma unroll
            for (int p = 0; p < NT / 2; p++) {
                unsigned r0, r1, r2, r3;
                LDMX4(r0, r1, r2, r3,
                      cur + bOff + (unsigned)(p * 16) * WS_STRIDE_B + (unsigned)(ki * 32));
                b[2 * p][0] = r0; b[2 * p][1] = r1;
                b[2 * p + 1][0] = r2; b[2 * p + 1][1] = r3;
            }
#pragma unroll
            for (int mt = 0; mt < 2; mt++)
#pragma unroll
                for (int nt = 0; nt < NT; nt++)
                    MMA16816(acc[mt][nt], a[mt], b[nt]);
        }
        __syncthreads();
    }
}

// ---------------------------------------------------------------------------
// full 512-col layer: GEMM (4 chunks) + bias + LN + act, in-place into A.
// ACT: 0 none, 1 relu, 2 silu.  sPb: [bias|gamma|beta] each 512 floats.
template <int KDIM, int ACT>
__device__ __forceinline__ void layer(const __half* __restrict__ WTg,
                                      const float* __restrict__ sPb,
                                      unsigned sbA, unsigned sbW,
                                      float* sSum, float* sSq,
                                      int tid, int lane, int mi, int ni)
{
    const int qp = lane & 3, g = lane >> 2;
    if (tid < 128) { sSum[tid] = 0.f; sSq[tid] = 0.f; }

    float srow[4] = {0.f, 0.f, 0.f, 0.f};
    float ssqr[4] = {0.f, 0.f, 0.f, 0.f};
    unsigned xs[128];

#pragma unroll
    for (int ch = 0; ch < 4; ch++) {
        float acc[2][8][4];
        gemm_chunk<8>(WTg, KDIM, 128, ch * 128, sbA, sbW, acc, tid, lane, mi, ni);
#pragma unroll
        for (int mt = 0; mt < 2; mt++)
#pragma unroll
            for (int nt = 0; nt < 8; nt++)
#pragma unroll
                for (int rh = 0; rh < 2; rh++) {
                    const int c0 = ch * 128 + ni * 64 + nt * 8 + qp * 2;
                    float x0 = acc[mt][nt][rh * 2]     + sPb[c0];
                    float x1 = acc[mt][nt][rh * 2 + 1] + sPb[c0 + 1];
                    const int s = mt * 2 + rh;
                    srow[s] += x0 + x1;
                    ssqr[s] += x0 * x0 + x1 * x1;
                    __half2 hp = __floats2half2_rn(x0, x1);
                    xs[ch * 32 + mt * 16 + nt * 2 + rh] = *(unsigned*)&hp;
                }
    }

#pragma unroll
    for (int s = 0; s < 4; s++) {
        srow[s] += __shfl_xor_sync(0xffffffffu, srow[s], 1);
        srow[s] += __shfl_xor_sync(0xffffffffu, srow[s], 2);
        ssqr[s] += __shfl_xor_sync(0xffffffffu, ssqr[s], 1);
        ssqr[s] += __shfl_xor_sync(0xffffffffu, ssqr[s], 2);
    }
    if (qp == 0) {
#pragma unroll
        for (int s = 0; s < 4; s++) {
            const int row = mi * 32 + (s >> 1) * 16 + (s & 1) * 8 + g;
            atomicAdd(&sSum[row], srow[s]);
            atomicAdd(&sSq[row],  ssqr[s]);
        }
    }
    __syncthreads();

    float mu[4], rs[4];
#pragma unroll
    for (int s = 0; s < 4; s++) {
        const int row = mi * 32 + (s >> 1) * 16 + (s & 1) * 8 + g;
        float m = sSum[row] * (1.f / 512.f);
        float v = fmaxf(sSq[row] * (1.f / 512.f) - m * m, 0.f);
        mu[s] = m; rs[s] = rsqrtf(v + EPSV);
    }
    const float* sG  = sPb + 512;
    const float* sBe = sPb + 1024;
#pragma unroll
    for (int ch = 0; ch < 4; ch++)
#pragma unroll
        for (int mt = 0; mt < 2; mt++)
#pragma unroll
            for (int nt = 0; nt < 8; nt++)
#pragma unroll
                for (int rh = 0; rh < 2; rh++) {
                    const int s = mt * 2 + rh;
                    const int c0 = ch * 128 + ni * 64 + nt * 8 + qp * 2;
                    float2 xr = __half22float2(
                        *(__half2*)&xs[ch * 32 + mt * 16 + nt * 2 + rh]);
                    float n0 = (xr.x - mu[s]) * rs[s] * sG[c0]     + sBe[c0];
                    float n1 = (xr.y - mu[s]) * rs[s] * sG[c0 + 1] + sBe[c0 + 1];
                    if (ACT == 1) { n0 = fmaxf(n0, 0.f); n1 = fmaxf(n1, 0.f); }
                    else if (ACT == 2) {
                        n0 = n0 / (1.f + __expf(-n0));
                        n1 = n1 / (1.f + __expf(-n1));
                    }
                    __half2 hp = __floats2half2_rn(n0, n1);
                    const int row = mi * 32 + mt * 16 + rh * 8 + g;
                    STS32(sbA + (unsigned)(row * A_STRIDE_B + c0 * 2), *(unsigned*)&hp);
                }
    __syncthreads();
}

// ---------------------------------------------------------------------------
__global__ void __launch_bounds__(THREADS, 1)
ifs_main(const float* __restrict__ z,
         const float* __restrict__ b1, const float* __restrict__ g1,
         const float* __restrict__ be1,
         const float* __restrict__ ba, const float* __restrict__ ga,
         const float* __restrict__ bea,
         const float* __restrict__ bb, const float* __restrict__ gb,
         const float* __restrict__ beb,
         const float* __restrict__ bout,
         float* __restrict__ out, int Btot)
{
    extern __shared__ char smc[];
    const unsigned sb  = smem_u32(smc);
    const unsigned sbW = sb + WS_OFF;
    const int tid = threadIdx.x, lane = tid & 31, wid = tid >> 5;
    const int mi = wid & 3, ni = wid >> 2;
    const int row0 = blockIdx.x * 128;

    float* sP   = (float*)(smc + P_OFF);
    float* sSum = (float*)(smc + RED_OFF);
    float* sSq  = sSum + 128;

    for (int i = tid; i < 512; i += THREADS) {
        sP[i]        = b1[i];  sP[512 + i]  = g1[i];  sP[1024 + i] = be1[i];
        sP[1536 + i] = ba[i];  sP[2048 + i] = ga[i];  sP[2560 + i] = bea[i];
        sP[3072 + i] = bb[i];  sP[3584 + i] = gb[i];  sP[4096 + i] = beb[i];
    }
    if (tid < 35) sP[4608 + tid] = bout[tid];

    // z -> A (fp16, row-major stride 520 halves)
    for (int i = tid; i < 128 * 64; i += THREADS) {
        int r = i >> 6, c4 = i & 63;
        float4 zv = *(const float4*)&z[(size_t)(row0 + r) * 256 + c4 * 4];
        __half2 h0 = __floats2half2_rn(zv.x, zv.y);
        __half2 h1 = __floats2half2_rn(zv.z, zv.w);
        STS64(sb + (unsigned)(r * A_STRIDE_B + c4 * 8),
              *(unsigned*)&h0, *(unsigned*)&h1);
    }
    __syncthreads();

    layer<256, 1>(g_Wt1, sP,        sb, sbW, sSum, sSq, tid, lane, mi, ni);

    // stash h (A) -> global scratch, coalesced 16B
    for (int c = tid; c < 128 * 64; c += THREADS) {
        int r = c >> 6, seg = c & 63;
        unsigned v0, v1, v2, v3;
        LDS128(v0, v1, v2, v3, sb + (unsigned)(r * A_STRIDE_B + seg * 16));
        uint4 vv = {v0, v1, v2, v3};
        *(uint4*)((char*)g_h + ((size_t)(row0 + r) * 512 + seg * 8) * 2) = vv;
    }
    __syncthreads();

    layer<512, 2>(g_Wta, sP + 1536, sb, sbW, sSum, sSq, tid, lane, mi, ni);
    layer<512, 0>(g_Wtb, sP + 3072, sb, sbW, sSum, sSq, tid, lane, mi, ni);

    // h2 = yb + h  (in-place in A)
    for (int c = tid; c < 128 * 64; c += THREADS) {
        int r = c >> 6, seg = c & 63;
        const unsigned aaddr = sb + (unsigned)(r * A_STRIDE_B + seg * 16);
        uint4 hv = *(const uint4*)((const char*)g_h +
                                   ((size_t)(row0 + r) * 512 + seg * 8) * 2);
        unsigned v0, v1, v2, v3;
        LDS128(v0, v1, v2, v3, aaddr);
        __half2 o0 = __hadd2(*(__half2*)&v0, *(__half2*)&hv.x);
        __half2 o1 = __hadd2(*(__half2*)&v1, *(__half2*)&hv.y);
        __half2 o2 = __hadd2(*(__half2*)&v2, *(__half2*)&hv.z);
        __half2 o3 = __hadd2(*(__half2*)&v3, *(__half2*)&hv.w);
        STS128(aaddr, *(unsigned*)&o0, *(unsigned*)&o1,
                      *(unsigned*)&o2, *(unsigned*)&o3);
    }
    __syncthreads();

    // ---- tail: x = h2 @ Wout + bout, then SVD clamp + softmax ----
    {
        float acc[2][4][4];
        gemm_chunk<4>(g_Wto, 512, 64, 0, sb, sbW, acc, tid, lane, mi, ni);

        float* sX = (float*)(smc + WS_OFF);      // [128][65] fp32 scratch
        const int qp = lane & 3, g = lane >> 2;
#pragma unroll
        for (int mt = 0; mt < 2; mt++)
#pragma unroll
            for (int nt = 0; nt < 4; nt++)
#pragma unroll
                for (int rh = 0; rh < 2; rh++) {
                    const int row = mi * 32 + mt * 16 + rh * 8 + g;
                    const int col = ni * 32 + nt * 8 + qp * 2;
                    sX[row * 65 + col]     = acc[mt][nt][rh * 2];
                    sX[row * 65 + col + 1] = acc[mt][nt][rh * 2 + 1];
                }
        __syncthreads();

        if (tid < 128) {
            const int r = tid;
            float x[35];
#pragma unroll
            for (int j = 0; j < 35; j++) x[j] = sX[r * 65 + j] + sP[4608 + j];

            const size_t gr = (size_t)(row0 + r);
            float* op = out + gr * 30;
#pragma unroll
            for (int t = 0; t < 5; t++) {
                float a = x[t * 6], b = x[t * 6 + 1], tx = x[t * 6 + 2];
                float c = x[t * 6 + 3], d = x[t * 6 + 4], ty = x[t * 6 + 5];
                float E = 0.5f * (a + d), F = 0.5f * (a - d);
                float G = 0.5f * (c + b), H = 0.5f * (c - b);
                float Q = sqrtf(E * E + H * H);
                float R = sqrtf(F * F + G * G);
                float s1 = Q + R, s2v = Q - R;
                float s1c = fminf(s1, THRESH);
                float s2c = fminf(fmaxf(s2v, -THRESH), THRESH);
                float Qc = 0.5f * (s1c + s2c), Rc = 0.5f * (s1c - s2c);
                float rQ = Qc / fmaxf(Q, 1e-30f);
                float rR = Rc / fmaxf(R, 1e-30f);
                op[t * 6 + 0] =  rQ * E + rR * F;
                op[t * 6 + 1] = -rQ * H + rR * G;
                op[t * 6 + 2] = tx;
                op[t * 6 + 3] =  rQ * H + rR * G;
                op[t * 6 + 4] =  rQ * E - rR * F;
                op[t * 6 + 5] = ty;
            }
            float mx = x[30];
#pragma unroll
            for (int k = 1; k < 5; k++) mx = fmaxf(mx, x[30 + k]);
            float e[5], ssum = 0.f;
#pragma unroll
            for (int k = 0; k < 5; k++) { e[k] = __expf(x[30 + k] - mx); ssum += e[k]; }
            float inv = 1.f / ssum;
            float* pp = out + (size_t)Btot * 30 + gr * 5;
#pragma unroll
            for (int k = 0; k < 5; k++) pp[k] = e[k] * inv;
        }
    }
}

// ---------------------------------------------------------------------------
// prep: WT[n][k] = fp16(W[k][n]); rows >= Nsrc zero-padded.
__global__ void prep_kernel(const float* __restrict__ W, int K, int Nsrc,
                            int nrows, int which)
{
    __half* WT = (which == 0) ? g_Wt1 : (which == 1) ? g_Wta
               : (which == 2) ? g_Wtb : g_Wto;
    int id = blockIdx.x * blockDim.x + threadIdx.x;
    if (id >= nrows * K) return;
    int n = id / K, k = id % K;
    float v = (n < Nsrc) ? W[(size_t)k * Nsrc + n] : 0.f;
    WT[(size_t)n * K + k] = __float2half_rn(v);
}

// ---------------------------------------------------------------------------
extern "C" void kernel_launch(void* const* d_in, const int* in_sizes, int n_in,
                              void* d_out, int out_size)
{
    const float* z    = (const float*)d_in[0];
    const float* W1   = (const float*)d_in[1];
    const float* b1   = (const float*)d_in[2];
    const float* g1   = (const float*)d_in[3];
    const float* be1  = (const float*)d_in[4];
    const float* Wa   = (const float*)d_in[5];
    const float* ba   = (const float*)d_in[6];
    const float* ga   = (const float*)d_in[7];
    const float* bea  = (const float*)d_in[8];
    const float* Wb   = (const float*)d_in[9];
    const float* bb   = (const float*)d_in[10];
    const float* gb   = (const float*)d_in[11];
    const float* beb  = (const float*)d_in[12];
    const float* Wout = (const float*)d_in[13];
    const float* bout = (const float*)d_in[14];
    float* out = (float*)d_out;

    const int Btot = in_sizes[0] / 256;

    prep_kernel<<<(512 * 256 + 255) / 256, 256>>>(W1,   256, 512, 512, 0);
    prep_kernel<<<(512 * 512 + 255) / 256, 256>>>(Wa,   512, 512, 512, 1);
    prep_kernel<<<(512 * 512 + 255) / 256, 256>>>(Wb,   512, 512, 512, 2);
    prep_kernel<<<(64  * 512 + 255) / 256, 256>>>(Wout, 512, 35,  64,  3);

    cudaFuncSetAttribute(ifs_main,
                         cudaFuncAttributeMaxDynamicSharedMemorySize, SMEM_BYTES);
    ifs_main<<<Btot / 128, THREADS, SMEM_BYTES>>>(
        z, b1, g1, be1, ba, ga, bea, bb, gb, beb, bout, out, Btot);
}